// round 6
// baseline (speedup 1.0000x reference)
#include <cuda_runtime.h>
#include <stdint.h>

#define N_NODES 100000
#define F4      16          // 64 floats = 16 float4 per node
#define NTOT4   (N_NODES * F4)

// Scratch (no device allocation allowed -> __device__ globals)
__device__ int g_counts[N_NODES];
__device__ int g_idx_is64;   // 1 if edge_index is int64, 0 if int32

// ---------------------------------------------------------------------------
// Kernel 0: detect index dtype. The harness's dtype contract only lists
// int32; the reference produces int64. Interpreting the first 1024 words as
// int64: all in [0, N_NODES) => int64; any out of range => int32 (a packed
// int32 pair as int64 is >= 2^32 unless the high index is 0, p = 1e-5).
// ---------------------------------------------------------------------------
__global__ void detect_kernel(const long long* __restrict__ ei, int n_words) {
    if (blockIdx.x == 0 && threadIdx.x == 0) {
        int n = n_words < 1024 ? n_words : 1024;
        int ok = 1;
        for (int i = 0; i < n; i++) {
            long long v = ei[i];
            if (v < 0 || v >= N_NODES) { ok = 0; break; }
        }
        g_idx_is64 = ok;
    }
}

// ---------------------------------------------------------------------------
// Kernel 1: zero the accumulator (reuses d_out) and the counts array.
// ---------------------------------------------------------------------------
__global__ void zero_kernel(float4* __restrict__ out) {
    int i = blockIdx.x * blockDim.x + threadIdx.x;
    if (i < NTOT4) out[i] = make_float4(0.f, 0.f, 0.f, 0.f);
    if (i < N_NODES) g_counts[i] = 0;
}

// ---------------------------------------------------------------------------
// Kernel 2: per-edge scatter. 16 lanes per edge; lane c handles float4 #c.
//   - one loader lane per 16-lane group reads (src, dst), shfl-broadcast
//   - ALL lanes reach the shuffles (clamped edge id; side effects predicated)
//   - gather nf[src] float4 (25.6 MB node table is L2-resident)
//   - red.global.add.v4.f32 into out[dst] (no return traffic)
//   - lane c==0 of the group bumps g_counts[dst]
// ---------------------------------------------------------------------------
__global__ void edge_kernel(const float4* __restrict__ nf,
                            const void*   __restrict__ eiv,
                            float4*       __restrict__ out,
                            int E) {
    long long t = (long long)blockIdx.x * blockDim.x + threadIdx.x;
    long long e = t >> 4;
    int c       = (int)(t & 15);
    int lane    = threadIdx.x & 31;

    bool valid = (e < E);
    long long ec = valid ? e : (long long)(E - 1);   // clamp for uniform shfl

    long long s = 0, d = 0;
    if ((lane & 15) == 0) {
        if (g_idx_is64) {
            const long long* ei = (const long long*)eiv;
            s = ei[ec];
            d = ei[(long long)E + ec];
        } else {
            const int* ei = (const int*)eiv;
            s = (long long)ei[ec];
            d = (long long)ei[(long long)E + ec];
        }
    }
    int leader = lane & 16;   // lane 0 for lanes 0-15, lane 16 for lanes 16-31
    s = __shfl_sync(0xffffffffu, s, leader);
    d = __shfl_sync(0xffffffffu, d, leader);

    if (!valid) return;
    // Hard bounds guard: no dereference can escape the buffers.
    if ((unsigned long long)s >= (unsigned long long)N_NODES ||
        (unsigned long long)d >= (unsigned long long)N_NODES) return;

    if (c == 0) atomicAdd(&g_counts[(int)d], 1);

    float4 v = __ldg(&nf[s * F4 + c]);
    float4* p = &out[d * F4 + c];
    asm volatile("red.global.add.v4.f32 [%0], {%1, %2, %3, %4};"
                 :: "l"(p), "f"(v.x), "f"(v.y), "f"(v.z), "f"(v.w)
                 : "memory");
}

// ---------------------------------------------------------------------------
// Kernel 3: finalize.
//   messages use src+dest, and dest feature for node i is nf[i]:
//   aggregated[i] = (sum_src + cnt*nf[i]) / max(cnt,1)
//   out[i] = nf[i] + aggregated[i] = cnt>0 ? 2*nf[i] + sum_src/cnt : nf[i]
// ---------------------------------------------------------------------------
__global__ void final_kernel(const float4* __restrict__ nf,
                             float4* __restrict__ out) {
    int i = blockIdx.x * blockDim.x + threadIdx.x;
    if (i >= NTOT4) return;
    int node = i >> 4;
    int cnt  = g_counts[node];
    float4 f = nf[i];
    float4 r;
    if (cnt > 0) {
        float inv = 1.0f / (float)cnt;
        float4 a = out[i];
        r.x = 2.0f * f.x + a.x * inv;
        r.y = 2.0f * f.y + a.y * inv;
        r.z = 2.0f * f.z + a.z * inv;
        r.w = 2.0f * f.w + a.w * inv;
    } else {
        r = f;
    }
    out[i] = r;
}

// ---------------------------------------------------------------------------
extern "C" void kernel_launch(void* const* d_in, const int* in_sizes, int n_in,
                              void* d_out, int out_size) {
    // Pick input roles by element count (dtype-independent):
    //   node_features: 100000*64 = 6,400,000 elements (== out_size)
    //   edge_index:    2*E       = 3,200,000 elements
    int nf_i = (in_sizes[0] == out_size) ? 0 : 1;
    int ei_i = 1 - nf_i;

    const float4* nf  = (const float4*)d_in[nf_i];
    const void*   ei  = d_in[ei_i];
    float4*       out = (float4*)d_out;

    int E = in_sizes[ei_i] / 2;

    // 0) detect index dtype (reads at most 1024 8-byte words; E words exist
    //    even in the int32 case since 2*E int32 = E int64-sized words)
    detect_kernel<<<1, 32>>>((const long long*)ei, E);

    // 1) zero accumulator + counts
    {
        int threads = 256;
        int blocks = (NTOT4 + threads - 1) / threads;
        zero_kernel<<<blocks, threads>>>(out);
    }

    // 2) edge scatter: 16 threads per edge
    {
        long long total = (long long)E * 16;
        int threads = 256;
        int blocks = (int)((total + threads - 1) / threads);
        edge_kernel<<<blocks, threads>>>(nf, ei, out, E);
    }

    // 3) finalize
    {
        int threads = 256;
        int blocks = (NTOT4 + threads - 1) / threads;
        final_kernel<<<blocks, threads>>>(nf, out);
    }
}

// round 8
// speedup vs baseline: 1.2101x; 1.2101x over previous
#include <cuda_runtime.h>
#include <stdint.h>

#define N_NODES 100000
#define F4      16                       // 64 floats = 16 float4 per node
#define NTOT4   (N_NODES * F4)
#define E_MAX   2000000                  // CSR src buffer capacity (E = 1.6M)
#define SCAN_B  1024
#define NBLK    ((N_NODES + SCAN_B - 1) / SCAN_B)   // 98

// Scratch (no device allocation allowed -> __device__ globals)
__device__ int g_counts[N_NODES];        // in-degree
__device__ int g_row[N_NODES];           // CSR row start (exclusive prefix)
__device__ int g_cursor[N_NODES];        // scatter cursor
__device__ int g_srcbuf[E_MAX];          // src node id per edge, grouped by dst
__device__ int g_blocksum[NBLK];
__device__ int g_blockoff[NBLK];
__device__ int g_idx_is64;               // 1 = int64 indices, 0 = int32

// ---------------------------------------------------------------------------
// A: zero counts + parallel-ish dtype detect (64 independent batched loads,
// no serial break chain). int32 data read as int64 packs two indices: value
// >= 2^32 unless the high index is 0 (p = 1e-5 per word) -> 64 words suffice.
// ---------------------------------------------------------------------------
__global__ void prep_kernel(const long long* __restrict__ ei, int E) {
    int i = blockIdx.x * blockDim.x + threadIdx.x;
    if (i < N_NODES) g_counts[i] = 0;
    if (blockIdx.x == 0 && threadIdx.x == 0) {
        int n = E < 64 ? E : 64;
        int ok = 1;
        #pragma unroll
        for (int k = 0; k < 64; k++) {
            if (k < n) {
                long long v = ei[k];
                if (v < 0 || v >= N_NODES) ok = 0;
            }
        }
        g_idx_is64 = ok;
    }
}

__device__ __forceinline__ long long load_idx(const void* eiv, long long pos) {
    if (g_idx_is64) return ((const long long*)eiv)[pos];
    return (long long)((const int*)eiv)[pos];
}

// ---------------------------------------------------------------------------
// B: in-degree histogram over dst
// ---------------------------------------------------------------------------
__global__ void hist_kernel(const void* __restrict__ eiv, int E) {
    int e = blockIdx.x * blockDim.x + threadIdx.x;
    if (e >= E) return;
    long long d = load_idx(eiv, (long long)E + e);
    if ((unsigned long long)d < (unsigned long long)N_NODES)
        atomicAdd(&g_counts[(int)d], 1);
}

// ---------------------------------------------------------------------------
// C1/C2/C3: exclusive prefix sum of counts -> g_row; copy to g_cursor
// ---------------------------------------------------------------------------
__global__ void scan1_kernel() {
    __shared__ int sm[SCAN_B];
    int t = threadIdx.x;
    int i = blockIdx.x * SCAN_B + t;
    int v = (i < N_NODES) ? g_counts[i] : 0;
    sm[t] = v;
    __syncthreads();
    for (int off = 1; off < SCAN_B; off <<= 1) {
        int x = (t >= off) ? sm[t - off] : 0;
        __syncthreads();
        sm[t] += x;
        __syncthreads();
    }
    if (i < N_NODES) g_row[i] = sm[t] - v;            // exclusive within block
    if (t == SCAN_B - 1) g_blocksum[blockIdx.x] = sm[t];
}

__global__ void scan2_kernel() {
    if (threadIdx.x == 0) {
        int run = 0;
        for (int b = 0; b < NBLK; b++) { g_blockoff[b] = run; run += g_blocksum[b]; }
    }
}

__global__ void scan3_kernel() {
    int t = threadIdx.x;
    int i = blockIdx.x * SCAN_B + t;
    if (i < N_NODES) {
        int r = g_row[i] + g_blockoff[blockIdx.x];
        g_row[i] = r;
        g_cursor[i] = r;
    }
}

// ---------------------------------------------------------------------------
// D: scatter src ids into CSR buckets
// ---------------------------------------------------------------------------
__global__ void scatter_kernel(const void* __restrict__ eiv, int E) {
    int e = blockIdx.x * blockDim.x + threadIdx.x;
    if (e >= E) return;
    long long s = load_idx(eiv, e);
    long long d = load_idx(eiv, (long long)E + e);
    if ((unsigned long long)s >= (unsigned long long)N_NODES ||
        (unsigned long long)d >= (unsigned long long)N_NODES) return;
    int pos = atomicAdd(&g_cursor[(int)d], 1);
    if (pos >= 0 && pos < E_MAX) g_srcbuf[pos] = (int)s;
}

// ---------------------------------------------------------------------------
// E: aggregate + finalize, fused. 16 lanes per node, lane c owns float4 #c.
// Batch-load 16 src ids coalesced, shfl-broadcast within the 16-lane segment
// (segment-local mask + width=16: the two warp halves diverge safely).
//   out[i] = cnt>0 ? 2*nf[i] + sum_src/cnt : nf[i]
// Output written exactly once -> no zero pass, no atomics, no final pass.
// ---------------------------------------------------------------------------
__global__ void aggregate_kernel(const float4* __restrict__ nf,
                                 float4* __restrict__ out) {
    int t = blockIdx.x * blockDim.x + threadIdx.x;
    int node = t >> 4;
    int c    = t & 15;
    if (node >= N_NODES) return;
    unsigned gmask = 0xFFFFu << (threadIdx.x & 16);

    int row = g_row[node];
    int cnt = g_counts[node];

    float4 acc = make_float4(0.f, 0.f, 0.f, 0.f);
    for (int base = 0; base < cnt; base += 16) {
        int k  = base + c;
        int id = (k < cnt) ? g_srcbuf[row + k] : 0;   // coalesced 64B per group
        int m  = cnt - base; if (m > 16) m = 16;
        for (int j = 0; j < m; j++) {
            int s = __shfl_sync(gmask, id, j, 16);
            float4 v = __ldg(&nf[(long long)s * F4 + c]);
            acc.x += v.x; acc.y += v.y; acc.z += v.z; acc.w += v.w;
        }
    }

    float4 f = nf[(long long)node * F4 + c];
    float4 r;
    if (cnt > 0) {
        float inv = 1.0f / (float)cnt;
        r.x = 2.0f * f.x + acc.x * inv;
        r.y = 2.0f * f.y + acc.y * inv;
        r.z = 2.0f * f.z + acc.z * inv;
        r.w = 2.0f * f.w + acc.w * inv;
    } else {
        r = f;
    }
    out[(long long)node * F4 + c] = r;
}

// ---------------------------------------------------------------------------
// Fallback path (E > E_MAX): R6's passing direct-RED design.
// ---------------------------------------------------------------------------
__global__ void fb_zero_kernel(float4* __restrict__ out) {
    int i = blockIdx.x * blockDim.x + threadIdx.x;
    if (i < NTOT4) out[i] = make_float4(0.f, 0.f, 0.f, 0.f);
}

__global__ void fb_edge_kernel(const float4* __restrict__ nf,
                               const void*   __restrict__ eiv,
                               float4*       __restrict__ out, int E) {
    long long t = (long long)blockIdx.x * blockDim.x + threadIdx.x;
    long long e = t >> 4;
    int c    = (int)(t & 15);
    int lane = threadIdx.x & 31;
    bool valid = (e < E);
    long long ec = valid ? e : (long long)(E - 1);
    long long s = 0, d = 0;
    if ((lane & 15) == 0) {
        s = load_idx(eiv, ec);
        d = load_idx(eiv, (long long)E + ec);
    }
    int leader = lane & 16;
    s = __shfl_sync(0xffffffffu, s, leader);
    d = __shfl_sync(0xffffffffu, d, leader);
    if (!valid) return;
    if ((unsigned long long)s >= (unsigned long long)N_NODES ||
        (unsigned long long)d >= (unsigned long long)N_NODES) return;
    if (c == 0) atomicAdd(&g_counts[(int)d], 1);
    float4 v = __ldg(&nf[s * F4 + c]);
    float4* p = &out[d * F4 + c];
    asm volatile("red.global.add.v4.f32 [%0], {%1, %2, %3, %4};"
                 :: "l"(p), "f"(v.x), "f"(v.y), "f"(v.z), "f"(v.w) : "memory");
}

__global__ void fb_final_kernel(const float4* __restrict__ nf,
                                float4* __restrict__ out) {
    int i = blockIdx.x * blockDim.x + threadIdx.x;
    if (i >= NTOT4) return;
    int cnt = g_counts[i >> 4];
    float4 f = nf[i];
    float4 r;
    if (cnt > 0) {
        float inv = 1.0f / (float)cnt;
        float4 a = out[i];
        r.x = 2.0f * f.x + a.x * inv;
        r.y = 2.0f * f.y + a.y * inv;
        r.z = 2.0f * f.z + a.z * inv;
        r.w = 2.0f * f.w + a.w * inv;
    } else r = f;
    out[i] = r;
}

// ---------------------------------------------------------------------------
extern "C" void kernel_launch(void* const* d_in, const int* in_sizes, int n_in,
                              void* d_out, int out_size) {
    // Role selection by element count (dtype-independent):
    //   node_features: 6,400,000 elements (== out_size); edge_index: 2*E
    int nf_i = (in_sizes[0] == out_size) ? 0 : 1;
    int ei_i = 1 - nf_i;

    const float4* nf  = (const float4*)d_in[nf_i];
    const void*   ei  = d_in[ei_i];
    float4*       out = (float4*)d_out;
    int E = in_sizes[ei_i] / 2;

    prep_kernel<<<(N_NODES + 255) / 256, 256>>>((const long long*)ei, E);

    if (E <= E_MAX) {
        int eb = (E + 255) / 256;
        hist_kernel<<<eb, 256>>>(ei, E);
        scan1_kernel<<<NBLK, SCAN_B>>>();
        scan2_kernel<<<1, 32>>>();
        scan3_kernel<<<NBLK, SCAN_B>>>();
        scatter_kernel<<<eb, 256>>>(ei, E);
        aggregate_kernel<<<(NTOT4 + 255) / 256, 256>>>(nf, out);
    } else {
        fb_zero_kernel<<<(NTOT4 + 255) / 256, 256>>>(out);
        long long total = (long long)E * 16;
        fb_edge_kernel<<<(int)((total + 255) / 256), 256>>>(nf, ei, out, E);
        fb_final_kernel<<<(NTOT4 + 255) / 256, 256>>>(nf, out);
    }
}